// round 8
// baseline (speedup 1.0000x reference)
#include <cuda_runtime.h>
#include <cuda_bf16.h>
#include <math.h>

// ---------------------------------------------------------------------------
// Decoder: conv3x3(256->128) -> deform_conv -> conv3x3(128->128) -> BN ->
// exact GELU -> mask conv(128->1).  B=8, C=128, H=W=56.
// Internal layout NHWC.  Hot loops use packed fma.rn.f32x2 (FFMA2) with the
// reduction (ci) dimension packed in 64-bit lanes: both operands loaded as
// LDS64 from ci-contiguous smem, no pack instructions in the inner loop.
// ---------------------------------------------------------------------------

#define H 56
#define W 56
#define B 8
#define C 128
#define NPIX 3136
#define NTOT 25088

typedef unsigned long long ull;

__device__ __forceinline__ void ffma2(ull& d, ull a, ull b) {
    asm("fma.rn.f32x2 %0, %1, %2, %0;" : "+l"(d) : "l"(a), "l"(b));
}
__device__ __forceinline__ float unpack_sum(ull v) {
    float lo, hi;
    asm("mov.b64 {%0, %1}, %2;" : "=r"(*(unsigned*)&lo), "=r"(*(unsigned*)&hi) : "l"(v));
    return lo + hi;
}
__device__ __forceinline__ ull pack2(float a, float b) {
    ull r;
    asm("mov.b64 %0, {%1, %2};" : "=l"(r) : "r"(*(unsigned*)&a), "r"(*(unsigned*)&b));
    return r;
}

// ---- scratch ----
__device__ float g_xy [NTOT * 256];   // concat(x,y) NHWC
__device__ float g_h1 [NTOT * 128];
__device__ float g_off[NTOT * 32];    // offsets (18 real, pad 32)
__device__ float g_h2 [NTOT * 128];
__device__ float g_h3 [NTOT * 128];
__device__ float g_w1t [256 * 9 * 128]; // [cc][k][co][ci8]
__device__ float g_offwt[128 * 9 * 32];
__device__ float g_w2t [128 * 9 * 128];
__device__ float g_dcnt[9 * 128 * 128]; // [tap][ci][co]
__device__ float g_sum[128], g_sq[128], g_scale[128], g_shift[128];

template<int TAG> __device__ __forceinline__ float* bufp() {
    if constexpr (TAG == 0) return g_xy;
    else if constexpr (TAG == 1) return g_h1;
    else if constexpr (TAG == 2) return g_off;
    else if constexpr (TAG == 3) return g_h2;
    else return g_h3;
}
template<int TAG> __device__ __forceinline__ const float* wbufp() {
    if constexpr (TAG == 0) return g_w1t;
    else if constexpr (TAG == 1) return g_offwt;
    else return g_w2t;
}

// ---------------------------------------------------------------------------
// prep: weights -> [ci_chunk][k][co][ci8] (ci8 innermost for f32x2 pairs)
// ---------------------------------------------------------------------------
__global__ void prep_kernel(const float* __restrict__ w1, const float* __restrict__ ow,
                            const float* __restrict__ w2, const float* __restrict__ dw) {
    int idx = blockIdx.x * blockDim.x + threadIdx.x;
    int stride = gridDim.x * blockDim.x;
    for (int i = idx; i < 256 * 9 * 128; i += stride) {
        int ci8 = i & 7, co = (i >> 3) & 127, k = (i >> 10) % 9, cc = i / (9 << 10);
        g_w1t[i] = w1[(co * 256 + cc * 8 + ci8) * 9 + k];
    }
    for (int i = idx; i < 128 * 9 * 32; i += stride) {
        int ci8 = i & 7, co = (i >> 3) & 31, k = (i >> 8) % 9, cc = i / (9 << 8);
        g_offwt[i] = (co < 18) ? ow[(co * 128 + cc * 8 + ci8) * 9 + k] : 0.f;
    }
    for (int i = idx; i < 128 * 9 * 128; i += stride) {
        int ci8 = i & 7, co = (i >> 3) & 127, k = (i >> 10) % 9, cc = i / (9 << 10);
        g_w2t[i] = w2[(co * 128 + cc * 8 + ci8) * 9 + k];
    }
    for (int i = idx; i < 9 * 128 * 128; i += stride) {
        int co = i % 128, ci = (i / 128) % 128, k = i / 16384;
        g_dcnt[i] = dw[(co * 128 + ci) * 9 + k];
    }
    for (int i = idx; i < 128; i += stride) { g_sum[i] = 0.f; g_sq[i] = 0.f; }
}

// ---------------------------------------------------------------------------
// NCHW -> NHWC of x,y into g_xy
// ---------------------------------------------------------------------------
__global__ void transpose_in_kernel(const float* __restrict__ x, const float* __restrict__ y) {
    __shared__ float s[64 * 129];
    int tid = threadIdx.x;
    int b = blockIdx.y;
    int p0 = blockIdx.x * 64;
    #pragma unroll
    for (int src = 0; src < 2; src++) {
        const float* in = src ? y : x;
        for (int idx = tid; idx < 64 * 128; idx += 256) {
            int c = idx >> 6, p = idx & 63;
            s[p * 129 + c] = in[(b * 128 + c) * NPIX + p0 + p];
        }
        __syncthreads();
        for (int idx = tid; idx < 64 * 128; idx += 256) {
            int p = idx >> 7, c = idx & 127;
            g_xy[(b * NPIX + p0 + p) * 256 + src * 128 + c] = s[p * 129 + c];
        }
        __syncthreads();
    }
}

// ---------------------------------------------------------------------------
// 3x3 SAME conv, NHWC, f32x2-packed over ci.
// Tile 8x8 px; thread = 4 px x CPT couts.  NTHR = 16*(CO_T/CPT) = 256.
// in_s: [100 px][12] (8 ci used, stride 12 floats = 48B, 16B aligned)
// w_s : [9 k][CO_T co][8 ci]
// ---------------------------------------------------------------------------
template<int CI, int CO_T, int COP, int CO_REAL, int CPT, int INB, int OUTB, int WB>
__global__ void conv3x3_kernel(const float* __restrict__ bias) {
    constexpr int NTHR = 16 * (CO_T / CPT);
    __shared__ float in_s[100 * 12];
    __shared__ float w_s[9 * CO_T * 8];

    const float* __restrict__ in  = bufp<INB>();
    float* __restrict__ out       = bufp<OUTB>();
    const float* __restrict__ wt  = wbufp<WB>();

    int tid = threadIdx.x;
    int ty = blockIdx.x / 7, tx = blockIdx.x % 7;
    int b = blockIdx.z;
    int cob = blockIdx.y * CO_T;
    int pg = tid & 15, cg = tid >> 4;
    int r = pg >> 1, cb = (pg & 1) * 4;
    int co_base = cg * CPT;
    int y0g = ty * 8 - 1, x0g = tx * 8 - 1;

    ull acc2[CPT][4];
    #pragma unroll
    for (int c = 0; c < CPT; c++)
        #pragma unroll
        for (int j = 0; j < 4; j++) acc2[c][j] = 0ull;

    for (int cc = 0; cc < CI / 8; cc++) {
        __syncthreads();
        // input chunk: 100 halo px x 8 ci, two float4 per px
        for (int idx = tid; idx < 200; idx += NTHR) {
            int px = idx >> 1, half = idx & 1;
            int py = px / 10, pxx = px % 10;
            int gy = y0g + py, gx = x0g + pxx;
            float4 v = make_float4(0.f, 0.f, 0.f, 0.f);
            if (gy >= 0 && gy < H && gx >= 0 && gx < W)
                v = *(const float4*)&in[((b * H + gy) * W + gx) * CI + cc * 8 + half * 4];
            *(float4*)&in_s[px * 12 + half * 4] = v;
        }
        // weight chunk: [9][CO_T][8]
        for (int i = tid; i < 9 * CO_T * 2; i += NTHR) {
            int k = i / (CO_T * 2), j = i % (CO_T * 2);
            *(float4*)&w_s[k * CO_T * 8 + j * 4] =
                *(const float4*)&wt[((cc * 9 + k) * COP + cob) * 8 + j * 4];
        }
        __syncthreads();

        #pragma unroll
        for (int ky = 0; ky < 3; ky++) {
            #pragma unroll
            for (int kx = 0; kx < 3; kx++) {
                const int k = ky * 3 + kx;
                const float* ib = &in_s[((r + ky) * 10 + cb + kx) * 12];
                const float* wb = &w_s[(k * CO_T + co_base) * 8];
                #pragma unroll
                for (int ci2 = 0; ci2 < 4; ci2++) {
                    ull ip[4];
                    #pragma unroll
                    for (int j = 0; j < 4; j++)
                        ip[j] = *(const ull*)&ib[j * 12 + ci2 * 2];
                    #pragma unroll
                    for (int c = 0; c < CPT; c++) {
                        ull wp = *(const ull*)&wb[c * 8 + ci2 * 2];
                        #pragma unroll
                        for (int j = 0; j < 4; j++)
                            ffma2(acc2[c][j], wp, ip[j]);
                    }
                }
            }
        }
    }

    float bv[CPT];
    #pragma unroll
    for (int c = 0; c < CPT; c++) {
        int co = cob + co_base + c;
        bv[c] = (co < CO_REAL) ? bias[co] : 0.f;
    }
    #pragma unroll
    for (int j = 0; j < 4; j++) {
        int gy = ty * 8 + r, gx = tx * 8 + cb + j;
        float* op = &out[((b * H + gy) * W + gx) * COP + cob + co_base];
        float res[CPT];
        #pragma unroll
        for (int c = 0; c < CPT; c++) res[c] = unpack_sum(acc2[c][j]) + bv[c];
        if constexpr (CPT == 4) {
            *(float4*)op = make_float4(res[0], res[1], res[2], res[3]);
        } else {
            *(float2*)op = make_float2(res[0], res[1]);
        }
    }
}

// ---------------------------------------------------------------------------
// Deformable conv: 4x4 px tile; bilinear gather to smem, then GEMM with
// co packed in f32x2 pairs (weights co-contiguous).
// ---------------------------------------------------------------------------
#define DEF_SAMP_FLOATS (16 * 1153)
#define DEF_WCHUNK (32 * 128)
#define DEF_SMEM_BYTES ((DEF_SAMP_FLOATS + DEF_WCHUNK) * 4)

__global__ void deform_kernel(const float* __restrict__ dcn_b) {
    extern __shared__ float dsm[];
    float* samp = dsm;
    float* w_s  = dsm + DEF_SAMP_FLOATS;

    int tid = threadIdx.x;
    int b = blockIdx.z;
    int ty = blockIdx.x / 14, tx = blockIdx.x % 14;

    // ---- gather ----
    int wid = tid >> 5, lane = tid & 31;
    for (int t = wid; t < 144; t += 8) {
        int pl = t / 9, tap = t % 9;
        int rr = pl >> 2, cl = pl & 3;
        int y = ty * 4 + rr, x = tx * 4 + cl;
        const float* ob = &g_off[((b * H + y) * W + x) * 32];
        float offy = ob[2 * tap], offx = ob[2 * tap + 1];
        float py = (float)y + (float)(tap / 3 - 1) + offy;
        float px = (float)x + (float)(tap % 3 - 1) + offx;
        float y0 = floorf(py), x0 = floorf(px);
        float y1 = y0 + 1.f, x1 = x0 + 1.f;
        float wy1 = py - y0, wy0 = 1.f - wy1;
        float wx1 = px - x0, wx0 = 1.f - wx1;
        float vy0 = (y0 >= 0.f && y0 <= 55.f) ? 1.f : 0.f;
        float vy1 = (y1 >= 0.f && y1 <= 55.f) ? 1.f : 0.f;
        float vx0 = (x0 >= 0.f && x0 <= 55.f) ? 1.f : 0.f;
        float vx1 = (x1 >= 0.f && x1 <= 55.f) ? 1.f : 0.f;
        float w00 = wy0 * wx0 * vy0 * vx0;
        float w01 = wy0 * wx1 * vy0 * vx1;
        float w10 = wy1 * wx0 * vy1 * vx0;
        float w11 = wy1 * wx1 * vy1 * vx1;
        int iy0 = (int)fminf(fmaxf(y0, 0.f), 55.f);
        int iy1 = (int)fminf(fmaxf(y1, 0.f), 55.f);
        int ix0 = (int)fminf(fmaxf(x0, 0.f), 55.f);
        int ix1 = (int)fminf(fmaxf(x1, 0.f), 55.f);
        const float* p00 = &g_h1[((b * H + iy0) * W + ix0) * 128];
        const float* p01 = &g_h1[((b * H + iy0) * W + ix1) * 128];
        const float* p10 = &g_h1[((b * H + iy1) * W + ix0) * 128];
        const float* p11 = &g_h1[((b * H + iy1) * W + ix1) * 128];
        float* sp = &samp[pl * 1153 + tap * 128];
        #pragma unroll
        for (int q = 0; q < 4; q++) {
            int ci = lane + q * 32;
            sp[ci] = w00 * p00[ci] + w01 * p01[ci] + w10 * p10[ci] + w11 * p11[ci];
        }
    }
    __syncthreads();

    // ---- GEMM (co packed) ----
    int pxl = tid & 15, cg = tid >> 4;
    int co0 = cg * 8;
    ull acc2[4];
    #pragma unroll
    for (int i = 0; i < 4; i++) acc2[i] = 0ull;

    for (int tap = 0; tap < 9; tap++) {
        for (int cc = 0; cc < 4; cc++) {
            __syncthreads();
            const float4* src = (const float4*)&g_dcnt[tap * 16384 + cc * 4096];
            float4* dst = (float4*)w_s;
            #pragma unroll
            for (int i = 0; i < 4; i++) dst[tid + i * 256] = src[tid + i * 256];
            __syncthreads();
            const float* sp = &samp[pxl * 1153 + tap * 128 + cc * 32];
            #pragma unroll
            for (int ci = 0; ci < 32; ci++) {
                float s = sp[ci];
                ull ss = pack2(s, s);
                const float* wr = &w_s[ci * 128 + co0];
                #pragma unroll
                for (int q = 0; q < 4; q++)
                    ffma2(acc2[q], *(const ull*)&wr[q * 2], ss);
            }
        }
    }

    int rr = pxl >> 2, cl = pxl & 3;
    int y = ty * 4 + rr, x = tx * 4 + cl;
    float* o = &g_h2[((b * H + y) * W + x) * 128 + co0];
    #pragma unroll
    for (int q = 0; q < 4; q++) {
        float lo, hi;
        asm("mov.b64 {%0, %1}, %2;" : "=r"(*(unsigned*)&lo), "=r"(*(unsigned*)&hi) : "l"(acc2[q]));
        *(float2*)&o[q * 2] = make_float2(lo + dcn_b[co0 + 2 * q], hi + dcn_b[co0 + 2 * q + 1]);
    }
}

// ---------------------------------------------------------------------------
__global__ void bn_stats_kernel() {
    int c = threadIdx.x;
    int p0 = blockIdx.x * 128;
    float s = 0.f, q = 0.f;
    for (int i = 0; i < 128; i++) {
        float v = g_h3[(p0 + i) * 128 + c];
        s += v; q += v * v;
    }
    atomicAdd(&g_sum[c], s);
    atomicAdd(&g_sq[c], q);
}

__global__ void bn_final_kernel(const float* __restrict__ gamma, const float* __restrict__ beta) {
    int c = threadIdx.x;
    float n = (float)NTOT;
    float mean = g_sum[c] / n;
    float var  = g_sq[c] / n - mean * mean;
    float sc = gamma[c] * rsqrtf(var + 1e-5f);
    g_scale[c] = sc;
    g_shift[c] = beta[c] - mean * sc;
}

__device__ __forceinline__ float gelu_exact(float v) {
    return 0.5f * v * (1.f + erff(v * 0.70710678118654752f));
}

__global__ void bn_gelu_out_kernel(float* __restrict__ out) {
    __shared__ float s[64 * 129];
    int tid = threadIdx.x;
    int b = blockIdx.y;
    int p0 = blockIdx.x * 64;
    for (int idx = tid; idx < 64 * 128; idx += 256) {
        int p = idx >> 7, c = idx & 127;
        float v = g_h3[(b * NPIX + p0 + p) * 128 + c];
        v = v * g_scale[c] + g_shift[c];
        s[p * 129 + c] = gelu_exact(v);
    }
    __syncthreads();
    for (int idx = tid; idx < 64 * 128; idx += 256) {
        int c = idx >> 6, p = idx & 63;
        out[(b * 128 + c) * NPIX + p0 + p] = s[p * 129 + c];
    }
}

__global__ void mask_conv_kernel(const float* __restrict__ mw, const float* __restrict__ mb,
                                 float* __restrict__ outm) {
    __shared__ float g_s[60 * 129];
    __shared__ float wm[1152];
    __shared__ float red[32 * 9];
    int tid = threadIdx.x;
    int b = blockIdx.y;
    int ty = blockIdx.x / 7, tx = blockIdx.x % 7;
    int y0 = ty * 4 - 1, x0 = tx * 8 - 1;

    for (int idx = tid; idx < 60 * 128; idx += 256) {
        int px = idx >> 7, ci = idx & 127;
        int gy = y0 + px / 10, gx = x0 + px % 10;
        float v = 0.f;
        if (gy >= 0 && gy < H && gx >= 0 && gx < W) {
            v = g_h3[((b * H + gy) * W + gx) * 128 + ci];
            v = gelu_exact(v * g_scale[ci] + g_shift[ci]);
        }
        g_s[px * 129 + ci] = v;
    }
    for (int i = tid; i < 1152; i += 256) wm[i] = mw[i];
    __syncthreads();

    int px = tid & 31, q = tid >> 5;
    int r = px >> 3, c = px & 7;
    float acc = 0.f;
    #pragma unroll
    for (int k = 0; k < 9; k++) {
        int hp = (r + k / 3) * 10 + c + k % 3;
        const float* gp = &g_s[hp * 129 + q * 16];
        #pragma unroll
        for (int ci = 0; ci < 16; ci++)
            acc += gp[ci] * wm[(q * 16 + ci) * 9 + k];
    }
    red[px * 9 + q] = acc;
    __syncthreads();
    if (tid < 32) {
        float s2 = 0.f;
        #pragma unroll
        for (int qq = 0; qq < 8; qq++) s2 += red[tid * 9 + qq];
        int gy = ty * 4 + (tid >> 3), gx = tx * 8 + (tid & 7);
        outm[b * NPIX + gy * W + gx] = s2 + mb[0];
    }
}

// ---------------------------------------------------------------------------
extern "C" void kernel_launch(void* const* d_in, const int* in_sizes, int n_in,
                              void* d_out, int out_size) {
    const float* x      = (const float*)d_in[0];
    const float* y      = (const float*)d_in[1];
    const float* conv_w = (const float*)d_in[2];
    const float* conv_b = (const float*)d_in[3];
    const float* off_w  = (const float*)d_in[4];
    const float* off_b  = (const float*)d_in[5];
    const float* dcn_w  = (const float*)d_in[6];
    const float* dcn_b  = (const float*)d_in[7];
    const float* conv2_w= (const float*)d_in[8];
    const float* conv2_b= (const float*)d_in[9];
    const float* bn_g   = (const float*)d_in[10];
    const float* bn_b   = (const float*)d_in[11];
    const float* mask_w = (const float*)d_in[12];
    const float* mask_b = (const float*)d_in[13];
    float* out = (float*)d_out;

    cudaFuncSetAttribute(deform_kernel, cudaFuncAttributeMaxDynamicSharedMemorySize,
                         DEF_SMEM_BYTES);

    prep_kernel<<<128, 256>>>(conv_w, off_w, conv2_w, dcn_w);
    transpose_in_kernel<<<dim3(49, 8), 256>>>(x, y);
    conv3x3_kernel<256, 64, 128, 128, 4, 0, 1, 0><<<dim3(49, 2, 8), 256>>>(conv_b);
    conv3x3_kernel<128, 32, 32, 18, 2, 1, 2, 1><<<dim3(49, 1, 8), 256>>>(off_b);
    deform_kernel<<<dim3(196, 1, 8), 256, DEF_SMEM_BYTES>>>(dcn_b);
    conv3x3_kernel<128, 64, 128, 128, 4, 3, 4, 2><<<dim3(49, 2, 8), 256>>>(conv2_b);
    bn_stats_kernel<<<196, 128>>>();
    bn_final_kernel<<<1, 128>>>(bn_g, bn_b);
    bn_gelu_out_kernel<<<dim3(49, 8), 256>>>(out);
    mask_conv_kernel<<<dim3(98, 8), 256>>>(mask_w, mask_b, out + 8 * 128 * NPIX);
}